// round 1
// baseline (speedup 1.0000x reference)
#include <cuda_runtime.h>
#include <math.h>

// Problem constants
#define NB 8
#define LQ 1024
#define SK 4096
#define DD 512
#define MQ  (NB * LQ)   // 8192 query rows
#define MKV (NB * SK)   // 32768 key/value rows
#define LN_EPS 1e-5f

// ---------------------------------------------------------------------------
// Scratch (device globals -- no allocation allowed)
// ---------------------------------------------------------------------------
__device__ float g_q  [(size_t)MQ  * DD];            // 16 MB
__device__ float g_k  [(size_t)MKV * DD];            // 64 MB
__device__ float g_v  [(size_t)MKV * DD];            // 64 MB
__device__ float g_q2 [MQ];
__device__ float g_k2 [MKV];
__device__ float g_sc [(size_t)NB * LQ * SK];        // 134 MB scores/attn
__device__ float g_msg[(size_t)MQ * DD];             // 16 MB
__device__ float g_tmp[(size_t)MQ * DD];             // 16 MB
__device__ float g_h  [(size_t)MQ * 2 * DD];         // 32 MB  [x | ln1]
__device__ float g_fc1[(size_t)MQ * 2 * DD];         // 32 MB

// ---------------------------------------------------------------------------
// Reductions
// ---------------------------------------------------------------------------
__device__ __forceinline__ float warpSum(float v) {
    #pragma unroll
    for (int o = 16; o > 0; o >>= 1) v += __shfl_xor_sync(0xffffffffu, v, o);
    return v;
}
__device__ __forceinline__ float warpMax(float v) {
    #pragma unroll
    for (int o = 16; o > 0; o >>= 1) v = fmaxf(v, __shfl_xor_sync(0xffffffffu, v, o));
    return v;
}
__device__ float blockSum(float v) {
    __shared__ float sh[8];
    __shared__ float tot;
    __syncthreads();
    int lane = threadIdx.x & 31, w = threadIdx.x >> 5;
    v = warpSum(v);
    if (lane == 0) sh[w] = v;
    __syncthreads();
    if (w == 0) {
        float t = (threadIdx.x < (blockDim.x >> 5)) ? sh[threadIdx.x] : 0.f;
        t = warpSum(t);
        if (threadIdx.x == 0) tot = t;
    }
    __syncthreads();
    return tot;
}
__device__ float blockMax(float v) {
    __shared__ float sh[8];
    __shared__ float tot;
    __syncthreads();
    int lane = threadIdx.x & 31, w = threadIdx.x >> 5;
    v = warpMax(v);
    if (lane == 0) sh[w] = v;
    __syncthreads();
    if (w == 0) {
        float t = (threadIdx.x < (blockDim.x >> 5)) ? sh[threadIdx.x] : -INFINITY;
        t = warpMax(t);
        if (threadIdx.x == 0) tot = t;
    }
    __syncthreads();
    return tot;
}

// ---------------------------------------------------------------------------
// Generic tiled SGEMM: C[M,Nc] = A[M,K] @ B  (B is [K,Nc] if !TRANSB,
// [Nc,K] if TRANSB).  All of M,Nc multiples of 128, K multiple of 16.
// Batched via blockIdx.z with element strides sA/sB/sC.
// 256 threads, 128x128 block tile, 16 k-slice, 8x8 per-thread microtile.
// ---------------------------------------------------------------------------
constexpr int BM = 128, BN = 128, BK = 16;

template <bool TRANSB, bool RELU>
__global__ __launch_bounds__(256) void sgemm_k(
    const float* __restrict__ A, const float* __restrict__ B,
    float* __restrict__ C, int M, int Nc, int K,
    long sA, long sB, long sC)
{
    A += (long)blockIdx.z * sA;
    B += (long)blockIdx.z * sB;
    C += (long)blockIdx.z * sC;

    __shared__ float As[BK][BM + 4];
    __shared__ float Bs[BK][BN + 4];

    const int tid = threadIdx.x;
    const int tx = tid & 15, ty = tid >> 4;
    const int row0 = blockIdx.y * BM;
    const int col0 = blockIdx.x * BN;

    float acc[8][8];
    #pragma unroll
    for (int i = 0; i < 8; i++)
        #pragma unroll
        for (int j = 0; j < 8; j++) acc[i][j] = 0.f;

    for (int k0 = 0; k0 < K; k0 += BK) {
        // Load A tile (BMxBK), stored transposed As[k][m]
        #pragma unroll
        for (int i = 0; i < 2; i++) {
            int idx = tid + i * 256;
            int m = idx >> 2, k4 = (idx & 3) << 2;
            float4 a = *(const float4*)(A + (long)(row0 + m) * K + k0 + k4);
            As[k4 + 0][m] = a.x; As[k4 + 1][m] = a.y;
            As[k4 + 2][m] = a.z; As[k4 + 3][m] = a.w;
        }
        if (TRANSB) {
            // B row-major [Nc, K]: dot rows of A with rows of B
            #pragma unroll
            for (int i = 0; i < 2; i++) {
                int idx = tid + i * 256;
                int nn = idx >> 2, k4 = (idx & 3) << 2;
                float4 b = *(const float4*)(B + (long)(col0 + nn) * K + k0 + k4);
                Bs[k4 + 0][nn] = b.x; Bs[k4 + 1][nn] = b.y;
                Bs[k4 + 2][nn] = b.z; Bs[k4 + 3][nn] = b.w;
            }
        } else {
            // B row-major [K, Nc]
            #pragma unroll
            for (int i = 0; i < 2; i++) {
                int idx = tid + i * 256;
                int kk = idx >> 5, n4 = (idx & 31) << 2;
                *(float4*)&Bs[kk][n4] =
                    *(const float4*)(B + (long)(k0 + kk) * Nc + col0 + n4);
            }
        }
        __syncthreads();

        #pragma unroll
        for (int kk = 0; kk < BK; kk++) {
            float ar[8], br[8];
            *(float4*)&ar[0] = *(const float4*)&As[kk][ty * 8];
            *(float4*)&ar[4] = *(const float4*)&As[kk][ty * 8 + 4];
            *(float4*)&br[0] = *(const float4*)&Bs[kk][tx * 8];
            *(float4*)&br[4] = *(const float4*)&Bs[kk][tx * 8 + 4];
            #pragma unroll
            for (int i = 0; i < 8; i++)
                #pragma unroll
                for (int j = 0; j < 8; j++)
                    acc[i][j] = fmaf(ar[i], br[j], acc[i][j]);
        }
        __syncthreads();
    }

    #pragma unroll
    for (int i = 0; i < 8; i++) {
        long crow = (long)(row0 + ty * 8 + i) * Nc + col0 + tx * 8;
        #pragma unroll
        for (int j = 0; j < 8; j += 4) {
            float4 o;
            o.x = acc[i][j];     o.y = acc[i][j + 1];
            o.z = acc[i][j + 2]; o.w = acc[i][j + 3];
            if (RELU) {
                o.x = fmaxf(o.x, 0.f); o.y = fmaxf(o.y, 0.f);
                o.z = fmaxf(o.z, 0.f); o.w = fmaxf(o.w, 0.f);
            }
            *(float4*)(C + crow + j) = o;
        }
    }
}

// ---------------------------------------------------------------------------
// Row squared-norm: out[row] = sum_c X[row,c]^2   (cols = 512, 256 thr/row)
// ---------------------------------------------------------------------------
__global__ __launch_bounds__(256) void rownorm_k(
    const float* __restrict__ X, float* __restrict__ out)
{
    const float* x = X + (long)blockIdx.x * DD;
    float v0 = x[threadIdx.x];
    float v1 = x[threadIdx.x + 256];
    float s = blockSum(v0 * v0 + v1 * v1);
    if (threadIdx.x == 0) out[blockIdx.x] = s;
}

// ---------------------------------------------------------------------------
// dist = sqrt(max(q2 + k2 - 2*qk, 0)); softmax over S (in place on scores)
// One block (256 thr) per (n,l) row; 16 elements per thread.
// ---------------------------------------------------------------------------
__global__ __launch_bounds__(256) void softmax_k(
    float* __restrict__ scores,
    const float* __restrict__ q2, const float* __restrict__ k2)
{
    const int row = blockIdx.x;       // 0..MQ-1
    const int n = row / LQ;
    float* sc = scores + (long)row * SK;
    const float* k2n = k2 + (long)n * SK;
    const float qq = q2[row];

    float d[16];
    float mx = -INFINITY;
    #pragma unroll
    for (int i = 0; i < 16; i++) {
        int j = threadIdx.x + i * 256;
        float qk = sc[j];
        float t = fmaxf(qq + k2n[j] - 2.f * qk, 0.f);
        float dist = sqrtf(t);
        d[i] = dist;
        mx = fmaxf(mx, dist);
    }
    mx = blockMax(mx);

    float s = 0.f;
    #pragma unroll
    for (int i = 0; i < 16; i++) {
        d[i] = expf(d[i] - mx);
        s += d[i];
    }
    s = blockSum(s);
    float inv = 1.f / s;
    #pragma unroll
    for (int i = 0; i < 16; i++) {
        int j = threadIdx.x + i * 256;
        sc[j] = d[i] * inv;
    }
}

// ---------------------------------------------------------------------------
// LayerNorm(mm) -> right half of h; copy x -> left half of h.
// One block (256 thr) per row, 2 elements per thread.
// ---------------------------------------------------------------------------
__global__ __launch_bounds__(256) void ln1_pack_k(
    const float* __restrict__ mm, const float* __restrict__ x,
    const float* __restrict__ g, const float* __restrict__ b,
    float* __restrict__ h)
{
    const int row = blockIdx.x;
    const float* m = mm + (long)row * DD;
    const int c0 = threadIdx.x, c1 = threadIdx.x + 256;
    float v0 = m[c0], v1 = m[c1];
    float mean = blockSum(v0 + v1) * (1.f / DD);
    float var  = blockSum(v0 * v0 + v1 * v1) * (1.f / DD) - mean * mean;
    float inv = rsqrtf(var + LN_EPS);

    float* hr = h + (long)row * (2 * DD);
    const float* xr = x + (long)row * DD;
    hr[c0] = xr[c0];
    hr[c1] = xr[c1];
    hr[DD + c0] = (v0 - mean) * inv * g[c0] + b[c0];
    hr[DD + c1] = (v1 - mean) * inv * g[c1] + b[c1];
}

// ---------------------------------------------------------------------------
// out = x + LayerNorm(t)   (per row of 512)
// ---------------------------------------------------------------------------
__global__ __launch_bounds__(256) void ln2_add_k(
    const float* __restrict__ t, const float* __restrict__ x,
    const float* __restrict__ g, const float* __restrict__ b,
    float* __restrict__ out)
{
    const int row = blockIdx.x;
    const float* tr = t + (long)row * DD;
    const int c0 = threadIdx.x, c1 = threadIdx.x + 256;
    float v0 = tr[c0], v1 = tr[c1];
    float mean = blockSum(v0 + v1) * (1.f / DD);
    float var  = blockSum(v0 * v0 + v1 * v1) * (1.f / DD) - mean * mean;
    float inv = rsqrtf(var + LN_EPS);

    const float* xr = x + (long)row * DD;
    float* orow = out + (long)row * DD;
    orow[c0] = xr[c0] + (v0 - mean) * inv * g[c0] + b[c0];
    orow[c1] = xr[c1] + (v1 - mean) * inv * g[c1] + b[c1];
}

// ---------------------------------------------------------------------------
// Launch
// ---------------------------------------------------------------------------
extern "C" void kernel_launch(void* const* d_in, const int* in_sizes, int n_in,
                              void* d_out, int out_size)
{
    const float* x   = (const float*)d_in[0];
    const float* src = (const float*)d_in[1];
    const float* Wq  = (const float*)d_in[2];
    const float* Wk  = (const float*)d_in[3];
    const float* Wv  = (const float*)d_in[4];
    const float* Wm  = (const float*)d_in[5];
    const float* W1  = (const float*)d_in[6];
    const float* W2  = (const float*)d_in[7];
    const float* g1  = (const float*)d_in[8];
    const float* b1  = (const float*)d_in[9];
    const float* g2  = (const float*)d_in[10];
    const float* b2  = (const float*)d_in[11];
    float* out = (float*)d_out;

    float *q, *k, *v, *q2, *k2, *sc, *msg, *tmp, *h, *fc1;
    cudaGetSymbolAddress((void**)&q,   g_q);
    cudaGetSymbolAddress((void**)&k,   g_k);
    cudaGetSymbolAddress((void**)&v,   g_v);
    cudaGetSymbolAddress((void**)&q2,  g_q2);
    cudaGetSymbolAddress((void**)&k2,  g_k2);
    cudaGetSymbolAddress((void**)&sc,  g_sc);
    cudaGetSymbolAddress((void**)&msg, g_msg);
    cudaGetSymbolAddress((void**)&tmp, g_tmp);
    cudaGetSymbolAddress((void**)&h,   g_h);
    cudaGetSymbolAddress((void**)&fc1, g_fc1);

    // 1. Projections
    sgemm_k<false, false><<<dim3(DD / BN, MQ / BM, 1), 256>>>(
        x, Wq, q, MQ, DD, DD, 0, 0, 0);
    sgemm_k<false, false><<<dim3(DD / BN, MKV / BM, 1), 256>>>(
        src, Wk, k, MKV, DD, DD, 0, 0, 0);
    sgemm_k<false, false><<<dim3(DD / BN, MKV / BM, 1), 256>>>(
        src, Wv, v, MKV, DD, DD, 0, 0, 0);

    // 2. Row squared norms
    rownorm_k<<<MQ, 256>>>(q, q2);
    rownorm_k<<<MKV, 256>>>(k, k2);

    // 3. Scores: qk[n,l,s] = q[n,l,:] . k[n,s,:]   (NT, batched over n)
    sgemm_k<true, false><<<dim3(SK / BN, LQ / BM, NB), 256>>>(
        q, k, sc, LQ, SK, DD,
        (long)LQ * DD, (long)SK * DD, (long)LQ * SK);

    // 4. dist + softmax (in place)
    softmax_k<<<MQ, 256>>>(sc, q2, k2);

    // 5. message = attn @ v   (NN, batched over n, K = S)
    sgemm_k<false, false><<<dim3(DD / BN, LQ / BM, NB), 256>>>(
        sc, v, msg, LQ, DD, SK,
        (long)LQ * SK, (long)SK * DD, (long)LQ * DD);

    // 6. mm = message @ Wm
    sgemm_k<false, false><<<dim3(DD / BN, MQ / BM, 1), 256>>>(
        msg, Wm, tmp, MQ, DD, DD, 0, 0, 0);

    // 7. h = [x | LayerNorm(mm; g1, b1)]
    ln1_pack_k<<<MQ, 256>>>(tmp, x, g1, b1, h);

    // 8. fc1 = relu(h @ W1)
    sgemm_k<false, true><<<dim3((2 * DD) / BN, MQ / BM, 1), 256>>>(
        h, W1, fc1, MQ, 2 * DD, 2 * DD, 0, 0, 0);

    // 9. fc2 = fc1 @ W2
    sgemm_k<false, false><<<dim3(DD / BN, MQ / BM, 1), 256>>>(
        fc1, W2, tmp, MQ, DD, 2 * DD, 0, 0, 0);

    // 10. out = x + LayerNorm(fc2; g2, b2)
    ln2_add_k<<<MQ, 256>>>(tmp, x, g2, b2, out);
}

// round 7
// speedup vs baseline: 3.0998x; 3.0998x over previous
#include <cuda_runtime.h>
#include <math.h>
#include <stdint.h>

// Problem constants
#define NB 8
#define LQ 1024
#define SK 4096
#define DD 512
#define MQ  (NB * LQ)   // 8192
#define MKV (NB * SK)   // 32768
#define LN_EPS 1e-5f

// ---------------------------------------------------------------------------
// Scratch (device globals -- no allocation allowed)
// ---------------------------------------------------------------------------
__device__ float g_q  [(size_t)MQ  * DD];
__device__ float g_k  [(size_t)MKV * DD];
__device__ float g_v  [(size_t)MKV * DD];
__device__ float g_q2 [MQ];
__device__ float g_k2 [MKV];
__device__ float g_sc [(size_t)NB * LQ * SK];
__device__ float g_msg[(size_t)MQ * DD];
__device__ float g_tmp[(size_t)MQ * DD];
__device__ float g_h  [(size_t)MQ * 2 * DD];
__device__ float g_fc1[(size_t)MQ * 2 * DD];

// ---------------------------------------------------------------------------
// PTX helpers (base compute_103 only -- no 'a' features)
// ---------------------------------------------------------------------------
__device__ __forceinline__ uint32_t cvta_smem(const void* p) {
    uint32_t a;
    asm("{ .reg .u64 t; cvta.to.shared.u64 t, %1; cvt.u32.u64 %0, t; }"
        : "=r"(a) : "l"(p));
    return a;
}
__device__ __forceinline__ void cp16(uint32_t d, const void* s) {
    asm volatile("cp.async.cg.shared.global [%0], [%1], 16;"
                 :: "r"(d), "l"(s));
}
__device__ __forceinline__ void cp_commit() {
    asm volatile("cp.async.commit_group;" ::: "memory");
}
template <int N>
__device__ __forceinline__ void cp_wait() {
    asm volatile("cp.async.wait_group %0;" :: "n"(N) : "memory");
}
__device__ __forceinline__ uint32_t f2tf32(float f) {
    uint32_t r;
    asm("cvt.rna.tf32.f32 %0, %1;" : "=r"(r) : "f"(f));
    return r;
}
__device__ __forceinline__ void mma_tf32(float* c, const uint32_t* a,
                                         const uint32_t* b) {
    asm volatile(
        "mma.sync.aligned.m16n8k8.row.col.f32.tf32.tf32.f32 "
        "{%0,%1,%2,%3}, {%4,%5,%6,%7}, {%8,%9}, {%0,%1,%2,%3};"
        : "+f"(c[0]), "+f"(c[1]), "+f"(c[2]), "+f"(c[3])
        : "r"(a[0]), "r"(a[1]), "r"(a[2]), "r"(a[3]),
          "r"(b[0]), "r"(b[1]));
}

// ---------------------------------------------------------------------------
// Universal GEMM on tf32 mma.sync:
//   C[M,Nc] = A[M,K] @ B      B = [K,Nc] if !TRANSB (NN), [Nc,K] if TRANSB (NT)
// Tile 128x128x32, 256 threads (8 warps 2x4), warp tile 64x32, 2-stage
// cp.async pipeline. M,Nc multiples of 128; K multiple of 32 and >= 64.
// ---------------------------------------------------------------------------
constexpr int AT = 128 * 36;   // A stage floats ([m][k] pad 36)
constexpr int BT = 128 * 36;   // B stage floats (NN 32*136=4352, NT 128*36=4608)
constexpr int STAGE = AT + BT;
#define SMEM_GEMM (2 * STAGE * 4)

template <bool TRANSB, bool RELU>
__global__ __launch_bounds__(256, 2) void tgemm(
    const float* __restrict__ A, const float* __restrict__ B,
    float* __restrict__ C, int M, int Nc, int K,
    long sA, long sB, long sC)
{
    extern __shared__ float sm[];
    A += (long)blockIdx.z * sA;
    B += (long)blockIdx.z * sB;
    C += (long)blockIdx.z * sC;

    const int tid = threadIdx.x, lane = tid & 31, wid = tid >> 5;
    const int wm = wid >> 2, wn = wid & 3;
    const int row0 = blockIdx.y * 128, col0 = blockIdx.x * 128;
    const uint32_t smb = cvta_smem(sm);

    float acc[4][4][4];
    #pragma unroll
    for (int i = 0; i < 4; i++)
        #pragma unroll
        for (int j = 0; j < 4; j++)
            #pragma unroll
            for (int l = 0; l < 4; l++) acc[i][j][l] = 0.f;

    const int nt = K >> 5;

    auto load_stage = [&](int s, int t) {
        const int k0 = t << 5;
        uint32_t sa = smb + (uint32_t)(s * STAGE) * 4u;
        const float* ga = A + (long)row0 * K + k0;
        #pragma unroll
        for (int i = 0; i < 4; i++) {
            int id = tid + (i << 8);
            int r = id >> 3, c = id & 7;
            cp16(sa + (uint32_t)(r * 36 + c * 4) * 4u,
                 ga + (long)r * K + (c << 2));
        }
        uint32_t sb = smb + (uint32_t)(s * STAGE + AT) * 4u;
        if (TRANSB) {
            const float* gb = B + (long)col0 * K + k0;
            #pragma unroll
            for (int i = 0; i < 4; i++) {
                int id = tid + (i << 8);
                int r = id >> 3, c = id & 7;
                cp16(sb + (uint32_t)(r * 36 + c * 4) * 4u,
                     gb + (long)r * K + (c << 2));
            }
        } else {
            // B tile: 32 rows (k) x 128 floats (n) = 1024 float4s, 4 per thread
            const float* gb = B + (long)k0 * Nc + col0;
            #pragma unroll
            for (int i = 0; i < 4; i++) {
                int id = tid + (i << 8);
                int r = id >> 5, c = id & 31;
                cp16(sb + (uint32_t)(r * 136 + c * 4) * 4u,
                     gb + (long)r * Nc + (c << 2));
            }
        }
        cp_commit();
    };

    load_stage(0, 0);
    load_stage(1, 1);

    for (int t = 0; t < nt; t++) {
        const int s = t & 1;
        if (t + 1 < nt) cp_wait<1>(); else cp_wait<0>();
        __syncthreads();
        const float* sa = sm + s * STAGE;
        const float* sb = sm + s * STAGE + AT;

        #pragma unroll
        for (int ks = 0; ks < 4; ks++) {
            const int kb = ks << 3;
            uint32_t af[4][4];
            #pragma unroll
            for (int ma = 0; ma < 4; ma++) {
                int r = wm * 64 + ma * 16 + (lane >> 2);
                int c = kb + (lane & 3);
                af[ma][0] = f2tf32(sa[r * 36 + c]);
                af[ma][1] = f2tf32(sa[(r + 8) * 36 + c]);
                af[ma][2] = f2tf32(sa[r * 36 + c + 4]);
                af[ma][3] = f2tf32(sa[(r + 8) * 36 + c + 4]);
            }
            uint32_t bf[4][2];
            #pragma unroll
            for (int na = 0; na < 4; na++) {
                int cl = wn * 32 + na * 8 + (lane >> 2);
                int kk = kb + (lane & 3);
                if (TRANSB) {
                    bf[na][0] = f2tf32(sb[cl * 36 + kk]);
                    bf[na][1] = f2tf32(sb[cl * 36 + kk + 4]);
                } else {
                    bf[na][0] = f2tf32(sb[kk * 136 + cl]);
                    bf[na][1] = f2tf32(sb[(kk + 4) * 136 + cl]);
                }
            }
            #pragma unroll
            for (int ma = 0; ma < 4; ma++)
                #pragma unroll
                for (int na = 0; na < 4; na++)
                    mma_tf32(acc[ma][na], af[ma], bf[na]);
        }
        __syncthreads();
        if (t + 2 < nt) load_stage(s, t + 2);
    }

    // Epilogue
    #pragma unroll
    for (int ma = 0; ma < 4; ma++) {
        int r = row0 + wm * 64 + ma * 16 + (lane >> 2);
        #pragma unroll
        for (int na = 0; na < 4; na++) {
            int cc = col0 + wn * 32 + na * 8 + 2 * (lane & 3);
            float2 v0 = make_float2(acc[ma][na][0], acc[ma][na][1]);
            float2 v1 = make_float2(acc[ma][na][2], acc[ma][na][3]);
            if (RELU) {
                v0.x = fmaxf(v0.x, 0.f); v0.y = fmaxf(v0.y, 0.f);
                v1.x = fmaxf(v1.x, 0.f); v1.y = fmaxf(v1.y, 0.f);
            }
            *(float2*)(C + (long)r * Nc + cc) = v0;
            *(float2*)(C + (long)(r + 8) * Nc + cc) = v1;
        }
    }
}

// ---------------------------------------------------------------------------
// Reductions + elementwise kernels
// ---------------------------------------------------------------------------
__device__ __forceinline__ float warpSum(float v) {
    #pragma unroll
    for (int o = 16; o > 0; o >>= 1) v += __shfl_xor_sync(0xffffffffu, v, o);
    return v;
}
__device__ __forceinline__ float warpMax(float v) {
    #pragma unroll
    for (int o = 16; o > 0; o >>= 1) v = fmaxf(v, __shfl_xor_sync(0xffffffffu, v, o));
    return v;
}
__device__ float blockSum(float v) {
    __shared__ float sh[8];
    __shared__ float tot;
    __syncthreads();
    int lane = threadIdx.x & 31, w = threadIdx.x >> 5;
    v = warpSum(v);
    if (lane == 0) sh[w] = v;
    __syncthreads();
    if (w == 0) {
        float t = (threadIdx.x < (blockDim.x >> 5)) ? sh[threadIdx.x] : 0.f;
        t = warpSum(t);
        if (threadIdx.x == 0) tot = t;
    }
    __syncthreads();
    return tot;
}
__device__ float blockMax(float v) {
    __shared__ float sh[8];
    __shared__ float tot;
    __syncthreads();
    int lane = threadIdx.x & 31, w = threadIdx.x >> 5;
    v = warpMax(v);
    if (lane == 0) sh[w] = v;
    __syncthreads();
    if (w == 0) {
        float t = (threadIdx.x < (blockDim.x >> 5)) ? sh[threadIdx.x] : -INFINITY;
        t = warpMax(t);
        if (threadIdx.x == 0) tot = t;
    }
    __syncthreads();
    return tot;
}

__global__ __launch_bounds__(256) void rownorm_k(
    const float* __restrict__ X, float* __restrict__ out)
{
    const float* x = X + (long)blockIdx.x * DD;
    float v0 = x[threadIdx.x];
    float v1 = x[threadIdx.x + 256];
    float s = blockSum(v0 * v0 + v1 * v1);
    if (threadIdx.x == 0) out[blockIdx.x] = s;
}

__global__ __launch_bounds__(256) void softmax_k(
    float* __restrict__ scores,
    const float* __restrict__ q2, const float* __restrict__ k2)
{
    const int row = blockIdx.x;
    const int n = row / LQ;
    float* sc = scores + (long)row * SK;
    const float* k2n = k2 + (long)n * SK;
    const float qq = q2[row];

    float d[16];
    float mx = -INFINITY;
    #pragma unroll
    for (int i = 0; i < 16; i++) {
        int j = threadIdx.x + i * 256;
        float qk = sc[j];
        float t = fmaxf(qq + k2n[j] - 2.f * qk, 0.f);
        float dist = sqrtf(t);
        d[i] = dist;
        mx = fmaxf(mx, dist);
    }
    mx = blockMax(mx);

    float s = 0.f;
    #pragma unroll
    for (int i = 0; i < 16; i++) {
        d[i] = expf(d[i] - mx);
        s += d[i];
    }
    s = blockSum(s);
    float inv = 1.f / s;
    #pragma unroll
    for (int i = 0; i < 16; i++) {
        int j = threadIdx.x + i * 256;
        sc[j] = d[i] * inv;
    }
}

__global__ __launch_bounds__(256) void ln1_pack_k(
    const float* __restrict__ mm, const float* __restrict__ x,
    const float* __restrict__ g, const float* __restrict__ b,
    float* __restrict__ h)
{
    const int row = blockIdx.x;
    const float* m = mm + (long)row * DD;
    const int c0 = threadIdx.x, c1 = threadIdx.x + 256;
    float v0 = m[c0], v1 = m[c1];
    float mean = blockSum(v0 + v1) * (1.f / DD);
    float var  = blockSum(v0 * v0 + v1 * v1) * (1.f / DD) - mean * mean;
    float inv = rsqrtf(var + LN_EPS);

    float* hr = h + (long)row * (2 * DD);
    const float* xr = x + (long)row * DD;
    hr[c0] = xr[c0];
    hr[c1] = xr[c1];
    hr[DD + c0] = (v0 - mean) * inv * g[c0] + b[c0];
    hr[DD + c1] = (v1 - mean) * inv * g[c1] + b[c1];
}

__global__ __launch_bounds__(256) void ln2_add_k(
    const float* __restrict__ t, const float* __restrict__ x,
    const float* __restrict__ g, const float* __restrict__ b,
    float* __restrict__ out)
{
    const int row = blockIdx.x;
    const float* tr = t + (long)row * DD;
    const int c0 = threadIdx.x, c1 = threadIdx.x + 256;
    float v0 = tr[c0], v1 = tr[c1];
    float mean = blockSum(v0 + v1) * (1.f / DD);
    float var  = blockSum(v0 * v0 + v1 * v1) * (1.f / DD) - mean * mean;
    float inv = rsqrtf(var + LN_EPS);

    const float* xr = x + (long)row * DD;
    float* orow = out + (long)row * DD;
    orow[c0] = xr[c0] + (v0 - mean) * inv * g[c0] + b[c0];
    orow[c1] = xr[c1] + (v1 - mean) * inv * g[c1] + b[c1];
}

// ---------------------------------------------------------------------------
// Launch
// ---------------------------------------------------------------------------
extern "C" void kernel_launch(void* const* d_in, const int* in_sizes, int n_in,
                              void* d_out, int out_size)
{
    const float* x   = (const float*)d_in[0];
    const float* src = (const float*)d_in[1];
    const float* Wq  = (const float*)d_in[2];
    const float* Wk  = (const float*)d_in[3];
    const float* Wv  = (const float*)d_in[4];
    const float* Wm  = (const float*)d_in[5];
    const float* W1  = (const float*)d_in[6];
    const float* W2  = (const float*)d_in[7];
    const float* g1  = (const float*)d_in[8];
    const float* b1  = (const float*)d_in[9];
    const float* g2  = (const float*)d_in[10];
    const float* b2  = (const float*)d_in[11];
    float* out = (float*)d_out;

    float *q, *k, *v, *q2, *k2, *sc, *msg, *tmp, *h, *fc1;
    cudaGetSymbolAddress((void**)&q,   g_q);
    cudaGetSymbolAddress((void**)&k,   g_k);
    cudaGetSymbolAddress((void**)&v,   g_v);
    cudaGetSymbolAddress((void**)&q2,  g_q2);
    cudaGetSymbolAddress((void**)&k2,  g_k2);
    cudaGetSymbolAddress((void**)&sc,  g_sc);
    cudaGetSymbolAddress((void**)&msg, g_msg);
    cudaGetSymbolAddress((void**)&tmp, g_tmp);
    cudaGetSymbolAddress((void**)&h,   g_h);
    cudaGetSymbolAddress((void**)&fc1, g_fc1);

    cudaFuncSetAttribute(tgemm<false, false>,
        cudaFuncAttributeMaxDynamicSharedMemorySize, SMEM_GEMM);
    cudaFuncSetAttribute(tgemm<true, false>,
        cudaFuncAttributeMaxDynamicSharedMemorySize, SMEM_GEMM);
    cudaFuncSetAttribute(tgemm<false, true>,
        cudaFuncAttributeMaxDynamicSharedMemorySize, SMEM_GEMM);

    // 1. Projections (NN: weights are [K,N] row-major)
    tgemm<false, false><<<dim3(DD / 128, MQ / 128, 1), 256, SMEM_GEMM>>>(
        x, Wq, q, MQ, DD, DD, 0, 0, 0);
    tgemm<false, false><<<dim3(DD / 128, MKV / 128, 1), 256, SMEM_GEMM>>>(
        src, Wk, k, MKV, DD, DD, 0, 0, 0);
    tgemm<false, false><<<dim3(DD / 128, MKV / 128, 1), 256, SMEM_GEMM>>>(
        src, Wv, v, MKV, DD, DD, 0, 0, 0);

    // 2. Row squared norms
    rownorm_k<<<MQ, 256>>>(q, q2);
    rownorm_k<<<MKV, 256>>>(k, k2);

    // 3. Scores: qk[n,l,s] = q . k  (NT, batched)
    tgemm<true, false><<<dim3(SK / 128, LQ / 128, NB), 256, SMEM_GEMM>>>(
        q, k, sc, LQ, SK, DD,
        (long)LQ * DD, (long)SK * DD, (long)LQ * SK);

    // 4. dist + softmax (in place)
    softmax_k<<<MQ, 256>>>(sc, q2, k2);

    // 5. message = attn @ v   (NN, v is [S,D] row-major, batched)
    tgemm<false, false><<<dim3(DD / 128, LQ / 128, NB), 256, SMEM_GEMM>>>(
        sc, v, msg, LQ, DD, SK,
        (long)LQ * SK, (long)SK * DD, (long)LQ * DD);

    // 6. mm = message @ Wm (NN)
    tgemm<false, false><<<dim3(DD / 128, MQ / 128, 1), 256, SMEM_GEMM>>>(
        msg, Wm, tmp, MQ, DD, DD, 0, 0, 0);

    // 7. h = [x | LayerNorm(mm)]
    ln1_pack_k<<<MQ, 256>>>(tmp, x, g1, b1, h);

    // 8. fc1 = relu(h @ W1) (NN)
    tgemm<false, true><<<dim3(2 * DD / 128, MQ / 128, 1), 256, SMEM_GEMM>>>(
        h, W1, fc1, MQ, 2 * DD, 2 * DD, 0, 0, 0);

    // 9. fc2 = fc1 @ W2 (NN)
    tgemm<false, false><<<dim3(DD / 128, MQ / 128, 1), 256, SMEM_GEMM>>>(
        fc1, W2, tmp, MQ, DD, 2 * DD, 0, 0, 0);

    // 10. out = x + LayerNorm(fc2)
    ln2_add_k<<<MQ, 256>>>(tmp, x, g2, b2, out);
}

// round 8
// speedup vs baseline: 4.3764x; 1.4118x over previous
#include <cuda_runtime.h>
#include <cuda_fp16.h>
#include <math.h>
#include <stdint.h>

// Problem constants
#define NB 8
#define LQ 1024
#define SK 4096
#define DD 512
#define MQ  (NB * LQ)   // 8192
#define MKV (NB * SK)   // 32768
#define LN_EPS 1e-5f

// ---------------------------------------------------------------------------
// Scratch (device globals)
// ---------------------------------------------------------------------------
__device__ __half g_xh  [(size_t)MQ  * DD];
__device__ __half g_srch[(size_t)MKV * DD];
__device__ __half g_qh  [(size_t)MQ  * DD];
__device__ __half g_kh  [(size_t)MKV * DD];
__device__ __half g_vh  [(size_t)MKV * DD];
__device__ __half g_vt  [(size_t)MKV * DD];          // per batch [D,S]
__device__ __half g_sch [(size_t)NB * LQ * SK];      // attn fp16
__device__ __half g_msgh[(size_t)MQ * DD];
__device__ __half g_hh  [(size_t)MQ * 2 * DD];
__device__ __half g_fc1h[(size_t)MQ * 2 * DD];
__device__ __half g_wqt [DD * DD];
__device__ __half g_wkt [DD * DD];
__device__ __half g_wvt [DD * DD];
__device__ __half g_wmt [DD * DD];
__device__ __half g_w1t [2 * DD * 2 * DD];
__device__ __half g_w2t [DD * 2 * DD];
__device__ float  g_sc  [(size_t)NB * LQ * SK];      // raw qk scores fp32
__device__ float  g_tmp [(size_t)MQ * DD];
__device__ float  g_q2  [MQ];
__device__ float  g_k2  [MKV];

// ---------------------------------------------------------------------------
// PTX helpers (base compute_103 only)
// ---------------------------------------------------------------------------
__device__ __forceinline__ uint32_t cvta_smem(const void* p) {
    uint32_t a;
    asm("{ .reg .u64 t; cvta.to.shared.u64 t, %1; cvt.u32.u64 %0, t; }"
        : "=r"(a) : "l"(p));
    return a;
}
__device__ __forceinline__ void cp16(uint32_t d, const void* s) {
    asm volatile("cp.async.cg.shared.global [%0], [%1], 16;"
                 :: "r"(d), "l"(s));
}
__device__ __forceinline__ void cp_commit() {
    asm volatile("cp.async.commit_group;" ::: "memory");
}
template <int N>
__device__ __forceinline__ void cp_wait() {
    asm volatile("cp.async.wait_group %0;" :: "n"(N) : "memory");
}
__device__ __forceinline__ void mma_fp16(float* c, const uint32_t* a,
                                         const uint32_t* b) {
    asm volatile(
        "mma.sync.aligned.m16n8k16.row.col.f32.f16.f16.f32 "
        "{%0,%1,%2,%3}, {%4,%5,%6,%7}, {%8,%9}, {%0,%1,%2,%3};"
        : "+f"(c[0]), "+f"(c[1]), "+f"(c[2]), "+f"(c[3])
        : "r"(a[0]), "r"(a[1]), "r"(a[2]), "r"(a[3]),
          "r"(b[0]), "r"(b[1]));
}

// ---------------------------------------------------------------------------
// fp16 NT GEMM: C[M,Nc] = A[M,K] @ B[Nc,K]^T   (fp32 accumulate)
// Block tile 128x256x32, 8 warps (2x4) of 64x64 warp tiles, 2-stage cp.async.
// M % 128 == 0, Nc % 256 == 0, K % 32 == 0, K >= 64.
// Smem rows padded to 40 halfs -> conflict-free 32-bit LDS fragments.
// ---------------------------------------------------------------------------
constexpr int ASTR = 40;                 // halfs per smem row
constexpr int AT_H = 128 * ASTR;         // 5120 halfs
constexpr int BT_H = 256 * ASTR;         // 10240 halfs
constexpr int STAGE_H = AT_H + BT_H;     // 15360 halfs = 30720 B
#define SMEM_GEMM (2 * STAGE_H * 2)      // 61440 B

template <bool RELU, typename TOUT>
__global__ __launch_bounds__(256, 1) void hgemm(
    const __half* __restrict__ A, const __half* __restrict__ B,
    TOUT* __restrict__ C, int M, int Nc, int K,
    long sA, long sB, long sC)
{
    extern __shared__ __align__(16) __half smh[];
    A += (long)blockIdx.z * sA;
    B += (long)blockIdx.z * sB;
    C += (long)blockIdx.z * sC;

    const int tid = threadIdx.x, lane = tid & 31, wid = tid >> 5;
    const int wm = wid >> 2, wn = wid & 3;       // 2 x 4 warp grid
    const int row0 = blockIdx.y * 128, col0 = blockIdx.x * 256;
    const uint32_t smb = cvta_smem(smh);

    float acc[4][8][4];
    #pragma unroll
    for (int i = 0; i < 4; i++)
        #pragma unroll
        for (int j = 0; j < 8; j++)
            #pragma unroll
            for (int l = 0; l < 4; l++) acc[i][j][l] = 0.f;

    const int nt = K >> 5;

    auto load_stage = [&](int s, int t) {
        const int k0 = t << 5;
        uint32_t sa = smb + (uint32_t)(s * STAGE_H * 2);
        const __half* ga = A + (long)row0 * K + k0;
        // A: 128 rows x 4 16B-chunks = 512, 2 per thread
        #pragma unroll
        for (int i = 0; i < 2; i++) {
            int id = tid + (i << 8);
            int r = id >> 2, c = id & 3;
            cp16(sa + (uint32_t)(r * 80 + c * 16), ga + (long)r * K + (c << 3));
        }
        uint32_t sb = smb + (uint32_t)((s * STAGE_H + AT_H) * 2);
        const __half* gb = B + (long)col0 * K + k0;
        // B: 256 rows x 4 chunks = 1024, 4 per thread
        #pragma unroll
        for (int i = 0; i < 4; i++) {
            int id = tid + (i << 8);
            int r = id >> 2, c = id & 3;
            cp16(sb + (uint32_t)(r * 80 + c * 16), gb + (long)r * K + (c << 3));
        }
        cp_commit();
    };

    load_stage(0, 0);
    load_stage(1, 1);

    for (int t = 0; t < nt; t++) {
        const int s = t & 1;
        if (t + 1 < nt) cp_wait<1>(); else cp_wait<0>();
        __syncthreads();
        const uint32_t* sa32 = (const uint32_t*)(smh + (size_t)s * STAGE_H);
        const uint32_t* sb32 = (const uint32_t*)(smh + (size_t)s * STAGE_H + AT_H);

        #pragma unroll
        for (int ks = 0; ks < 2; ks++) {
            const int kw = ks * 8 + (lane & 3);   // word offset within row
            uint32_t af[4][4];
            #pragma unroll
            for (int ma = 0; ma < 4; ma++) {
                int r = wm * 64 + ma * 16 + (lane >> 2);
                af[ma][0] = sa32[r * 20 + kw];
                af[ma][1] = sa32[(r + 8) * 20 + kw];
                af[ma][2] = sa32[r * 20 + kw + 4];
                af[ma][3] = sa32[(r + 8) * 20 + kw + 4];
            }
            uint32_t bf[8][2];
            #pragma unroll
            for (int na = 0; na < 8; na++) {
                int n = wn * 64 + na * 8 + (lane >> 2);
                bf[na][0] = sb32[n * 20 + kw];
                bf[na][1] = sb32[n * 20 + kw + 4];
            }
            #pragma unroll
            for (int ma = 0; ma < 4; ma++)
                #pragma unroll
                for (int na = 0; na < 8; na++)
                    mma_fp16(acc[ma][na], af[ma], bf[na]);
        }
        __syncthreads();
        if (t + 2 < nt) load_stage(s, t + 2);
    }

    // Epilogue
    #pragma unroll
    for (int ma = 0; ma < 4; ma++) {
        int r = row0 + wm * 64 + ma * 16 + (lane >> 2);
        #pragma unroll
        for (int na = 0; na < 8; na++) {
            int cc = col0 + wn * 64 + na * 8 + 2 * (lane & 3);
            float c0 = acc[ma][na][0], c1 = acc[ma][na][1];
            float c2 = acc[ma][na][2], c3 = acc[ma][na][3];
            if (RELU) {
                c0 = fmaxf(c0, 0.f); c1 = fmaxf(c1, 0.f);
                c2 = fmaxf(c2, 0.f); c3 = fmaxf(c3, 0.f);
            }
            if (sizeof(TOUT) == 2) {
                *(__half2*)((__half*)C + (long)r * Nc + cc) =
                    __floats2half2_rn(c0, c1);
                *(__half2*)((__half*)C + (long)(r + 8) * Nc + cc) =
                    __floats2half2_rn(c2, c3);
            } else {
                *(float2*)((float*)C + (long)r * Nc + cc) = make_float2(c0, c1);
                *(float2*)((float*)C + (long)(r + 8) * Nc + cc) = make_float2(c2, c3);
            }
        }
    }
}

// ---------------------------------------------------------------------------
// Conversion / transpose kernels
// ---------------------------------------------------------------------------
__global__ __launch_bounds__(256) void conv_f2h(
    const float* __restrict__ in, __half* __restrict__ out)
{
    long i = ((long)blockIdx.x * 256 + threadIdx.x) * 4;
    float4 v = *(const float4*)(in + i);
    *(__half2*)(out + i)     = __floats2half2_rn(v.x, v.y);
    *(__half2*)(out + i + 2) = __floats2half2_rn(v.z, v.w);
}

__global__ void trans_f2h(const float* __restrict__ in, __half* __restrict__ out,
                          int R, int C)
{
    __shared__ float t[32][33];
    int c0 = blockIdx.x * 32, r0 = blockIdx.y * 32;
    #pragma unroll
    for (int i = threadIdx.y; i < 32; i += 8)
        t[i][threadIdx.x] = in[(long)(r0 + i) * C + c0 + threadIdx.x];
    __syncthreads();
    #pragma unroll
    for (int i = threadIdx.y; i < 32; i += 8)
        out[(long)(c0 + i) * R + r0 + threadIdx.x] = __float2half_rn(t[threadIdx.x][i]);
}

__global__ void trans_h2h(const __half* __restrict__ in, __half* __restrict__ out,
                          int R, int C)
{
    __shared__ __half t[32][33];
    long bi = (long)blockIdx.z * R * C;
    int c0 = blockIdx.x * 32, r0 = blockIdx.y * 32;
    #pragma unroll
    for (int i = threadIdx.y; i < 32; i += 8)
        t[i][threadIdx.x] = in[bi + (long)(r0 + i) * C + c0 + threadIdx.x];
    __syncthreads();
    #pragma unroll
    for (int i = threadIdx.y; i < 32; i += 8)
        out[bi + (long)(c0 + i) * R + r0 + threadIdx.x] = t[threadIdx.x][i];
}

// ---------------------------------------------------------------------------
// Reductions
// ---------------------------------------------------------------------------
__device__ __forceinline__ float warpSum(float v) {
    #pragma unroll
    for (int o = 16; o > 0; o >>= 1) v += __shfl_xor_sync(0xffffffffu, v, o);
    return v;
}
__device__ __forceinline__ float warpMax(float v) {
    #pragma unroll
    for (int o = 16; o > 0; o >>= 1) v = fmaxf(v, __shfl_xor_sync(0xffffffffu, v, o));
    return v;
}
__device__ float blockSum(float v) {
    __shared__ float sh[8];
    __shared__ float tot;
    __syncthreads();
    int lane = threadIdx.x & 31, w = threadIdx.x >> 5;
    v = warpSum(v);
    if (lane == 0) sh[w] = v;
    __syncthreads();
    if (w == 0) {
        float t = (threadIdx.x < (blockDim.x >> 5)) ? sh[threadIdx.x] : 0.f;
        t = warpSum(t);
        if (threadIdx.x == 0) tot = t;
    }
    __syncthreads();
    return tot;
}
__device__ float blockMax(float v) {
    __shared__ float sh[8];
    __shared__ float tot;
    __syncthreads();
    int lane = threadIdx.x & 31, w = threadIdx.x >> 5;
    v = warpMax(v);
    if (lane == 0) sh[w] = v;
    __syncthreads();
    if (w == 0) {
        float t = (threadIdx.x < (blockDim.x >> 5)) ? sh[threadIdx.x] : -INFINITY;
        t = warpMax(t);
        if (threadIdx.x == 0) tot = t;
    }
    __syncthreads();
    return tot;
}

// ---------------------------------------------------------------------------
// Elementwise kernels
// ---------------------------------------------------------------------------
__global__ __launch_bounds__(256) void rownorm_h(
    const __half* __restrict__ X, float* __restrict__ out)
{
    const __half2* x = (const __half2*)(X + (long)blockIdx.x * DD);
    float2 f = __half22float2(x[threadIdx.x]);
    float s = blockSum(f.x * f.x + f.y * f.y);
    if (threadIdx.x == 0) out[blockIdx.x] = s;
}

__global__ __launch_bounds__(256) void softmax_k(
    const float* __restrict__ scores, __half* __restrict__ attn,
    const float* __restrict__ q2, const float* __restrict__ k2)
{
    const int row = blockIdx.x;
    const int n = row / LQ;
    const float* sc = scores + (long)row * SK;
    __half* ao = attn + (long)row * SK;
    const float* k2n = k2 + (long)n * SK;
    const float qq = q2[row];

    float d[16];
    float mx = -INFINITY;
    #pragma unroll
    for (int i = 0; i < 16; i++) {
        int j = threadIdx.x + i * 256;
        float qk = sc[j];
        float t = fmaxf(qq + k2n[j] - 2.f * qk, 0.f);
        float dist = sqrtf(t);
        d[i] = dist;
        mx = fmaxf(mx, dist);
    }
    mx = blockMax(mx);

    float s = 0.f;
    #pragma unroll
    for (int i = 0; i < 16; i++) {
        d[i] = expf(d[i] - mx);
        s += d[i];
    }
    s = blockSum(s);
    float inv = 1.f / s;
    #pragma unroll
    for (int i = 0; i < 16; i++) {
        int j = threadIdx.x + i * 256;
        ao[j] = __float2half_rn(d[i] * inv);
    }
}

__global__ __launch_bounds__(256) void ln1_pack_k(
    const float* __restrict__ mm, const float* __restrict__ x,
    const float* __restrict__ g, const float* __restrict__ b,
    __half* __restrict__ h)
{
    const int row = blockIdx.x;
    const float* m = mm + (long)row * DD;
    const int c0 = threadIdx.x, c1 = threadIdx.x + 256;
    float v0 = m[c0], v1 = m[c1];
    float mean = blockSum(v0 + v1) * (1.f / DD);
    float var  = blockSum(v0 * v0 + v1 * v1) * (1.f / DD) - mean * mean;
    float inv = rsqrtf(var + LN_EPS);

    __half* hr = h + (long)row * (2 * DD);
    const float* xr = x + (long)row * DD;
    hr[c0] = __float2half_rn(xr[c0]);
    hr[c1] = __float2half_rn(xr[c1]);
    hr[DD + c0] = __float2half_rn((v0 - mean) * inv * g[c0] + b[c0]);
    hr[DD + c1] = __float2half_rn((v1 - mean) * inv * g[c1] + b[c1]);
}

__global__ __launch_bounds__(256) void ln2_add_k(
    const float* __restrict__ t, const float* __restrict__ x,
    const float* __restrict__ g, const float* __restrict__ b,
    float* __restrict__ out)
{
    const int row = blockIdx.x;
    const float* tr = t + (long)row * DD;
    const int c0 = threadIdx.x, c1 = threadIdx.x + 256;
    float v0 = tr[c0], v1 = tr[c1];
    float mean = blockSum(v0 + v1) * (1.f / DD);
    float var  = blockSum(v0 * v0 + v1 * v1) * (1.f / DD) - mean * mean;
    float inv = rsqrtf(var + LN_EPS);

    const float* xr = x + (long)row * DD;
    float* orow = out + (long)row * DD;
    orow[c0] = xr[c0] + (v0 - mean) * inv * g[c0] + b[c0];
    orow[c1] = xr[c1] + (v1 - mean) * inv * g[c1] + b[c1];
}

// ---------------------------------------------------------------------------
// Launch
// ---------------------------------------------------------------------------
extern "C" void kernel_launch(void* const* d_in, const int* in_sizes, int n_in,
                              void* d_out, int out_size)
{
    const float* x   = (const float*)d_in[0];
    const float* src = (const float*)d_in[1];
    const float* Wq  = (const float*)d_in[2];
    const float* Wk  = (const float*)d_in[3];
    const float* Wv  = (const float*)d_in[4];
    const float* Wm  = (const float*)d_in[5];
    const float* W1  = (const float*)d_in[6];
    const float* W2  = (const float*)d_in[7];
    const float* g1  = (const float*)d_in[8];
    const float* b1  = (const float*)d_in[9];
    const float* g2  = (const float*)d_in[10];
    const float* b2  = (const float*)d_in[11];
    float* out = (float*)d_out;

    __half *xh, *srch, *qh, *kh, *vh, *vt, *sch, *msgh, *hh, *fc1h;
    __half *wqt, *wkt, *wvt, *wmt, *w1t, *w2t;
    float *sc, *tmp, *q2, *k2;
    cudaGetSymbolAddress((void**)&xh,   g_xh);
    cudaGetSymbolAddress((void**)&srch, g_srch);
    cudaGetSymbolAddress((void**)&qh,   g_qh);
    cudaGetSymbolAddress((void**)&kh,   g_kh);
    cudaGetSymbolAddress((void**)&vh,   g_vh);
    cudaGetSymbolAddress((void**)&vt,   g_vt);
    cudaGetSymbolAddress((void**)&sch,  g_sch);
    cudaGetSymbolAddress((void**)&msgh, g_msgh);
    cudaGetSymbolAddress((void**)&hh,   g_hh);
    cudaGetSymbolAddress((void**)&fc1h, g_fc1h);
    cudaGetSymbolAddress((void**)&wqt,  g_wqt);
    cudaGetSymbolAddress((void**)&wkt,  g_wkt);
    cudaGetSymbolAddress((void**)&wvt,  g_wvt);
    cudaGetSymbolAddress((void**)&wmt,  g_wmt);
    cudaGetSymbolAddress((void**)&w1t,  g_w1t);
    cudaGetSymbolAddress((void**)&w2t,  g_w2t);
    cudaGetSymbolAddress((void**)&sc,   g_sc);
    cudaGetSymbolAddress((void**)&tmp,  g_tmp);
    cudaGetSymbolAddress((void**)&q2,   g_q2);
    cudaGetSymbolAddress((void**)&k2,   g_k2);

    cudaFuncSetAttribute(hgemm<false, __half>,
        cudaFuncAttributeMaxDynamicSharedMemorySize, SMEM_GEMM);
    cudaFuncSetAttribute(hgemm<false, float>,
        cudaFuncAttributeMaxDynamicSharedMemorySize, SMEM_GEMM);
    cudaFuncSetAttribute(hgemm<true, __half>,
        cudaFuncAttributeMaxDynamicSharedMemorySize, SMEM_GEMM);

    dim3 t32(32, 8, 1);

    // 0. fp16 conversions / weight transposes
    conv_f2h<<<(MQ * DD) / 1024, 256>>>(x, xh);
    conv_f2h<<<(MKV * DD) / 1024, 256>>>(src, srch);
    trans_f2h<<<dim3(DD / 32, DD / 32), t32>>>(Wq, wqt, DD, DD);
    trans_f2h<<<dim3(DD / 32, DD / 32), t32>>>(Wk, wkt, DD, DD);
    trans_f2h<<<dim3(DD / 32, DD / 32), t32>>>(Wv, wvt, DD, DD);
    trans_f2h<<<dim3(DD / 32, DD / 32), t32>>>(Wm, wmt, DD, DD);
    trans_f2h<<<dim3(2 * DD / 32, 2 * DD / 32), t32>>>(W1, w1t, 2 * DD, 2 * DD);
    trans_f2h<<<dim3(DD / 32, 2 * DD / 32), t32>>>(W2, w2t, 2 * DD, DD);

    // 1. Projections (NT, fp16 out)
    hgemm<false, __half><<<dim3(DD / 256, MQ / 128, 1), 256, SMEM_GEMM>>>(
        xh, wqt, qh, MQ, DD, DD, 0, 0, 0);
    hgemm<false, __half><<<dim3(DD / 256, MKV / 128, 1), 256, SMEM_GEMM>>>(
        srch, wkt, kh, MKV, DD, DD, 0, 0, 0);
    hgemm<false, __half><<<dim3(DD / 256, MKV / 128, 1), 256, SMEM_GEMM>>>(
        srch, wvt, vh, MKV, DD, DD, 0, 0, 0);

    // 2. Row squared norms (from the same fp16 values the MMAs consume)
    rownorm_h<<<MQ, 256>>>(qh, q2);
    rownorm_h<<<MKV, 256>>>(kh, k2);

    // 3. v transpose per batch: [S,D] -> [D,S]
    trans_h2h<<<dim3(DD / 32, SK / 32, NB), t32>>>(vh, vt, SK, DD);

    // 4. Scores (fp32 out)
    hgemm<false, float><<<dim3(SK / 256, LQ / 128, NB), 256, SMEM_GEMM>>>(
        qh, kh, sc, LQ, SK, DD,
        (long)LQ * DD, (long)SK * DD, (long)LQ * SK);

    // 5. dist + softmax -> fp16 attn
    softmax_k<<<MQ, 256>>>(sc, sch, q2, k2);

    // 6. message = attn @ v  (NT with vt, fp16 out)
    hgemm<false, __half><<<dim3(DD / 256, LQ / 128, NB), 256, SMEM_GEMM>>>(
        sch, vt, msgh, LQ, DD, SK,
        (long)LQ * SK, (long)DD * SK, (long)LQ * DD);

    // 7. mm = message @ Wm (fp32 out)
    hgemm<false, float><<<dim3(DD / 256, MQ / 128, 1), 256, SMEM_GEMM>>>(
        msgh, wmt, tmp, MQ, DD, DD, 0, 0, 0);

    // 8. h = [x | LayerNorm(mm)] (fp16)
    ln1_pack_k<<<MQ, 256>>>(tmp, x, g1, b1, hh);

    // 9. fc1 = relu(h @ W1) (fp16 out)
    hgemm<true, __half><<<dim3(2 * DD / 256, MQ / 128, 1), 256, SMEM_GEMM>>>(
        hh, w1t, fc1h, MQ, 2 * DD, 2 * DD, 0, 0, 0);

    // 10. fc2 = fc1 @ W2 (fp32 out)
    hgemm<false, float><<<dim3(DD / 256, MQ / 128, 1), 256, SMEM_GEMM>>>(
        fc1h, w2t, tmp, MQ, DD, 2 * DD, 0, 0, 0);

    // 11. out = x + LayerNorm(fc2)
    ln2_add_k<<<MQ, 256>>>(tmp, x, g2, b2, out);
}

// round 9
// speedup vs baseline: 4.5130x; 1.0312x over previous
#include <cuda_runtime.h>
#include <cuda_fp16.h>
#include <math.h>
#include <stdint.h>

// Problem constants
#define NB 8
#define LQ 1024
#define SK 4096
#define DD 512
#define MQ  (NB * LQ)   // 8192
#define MKV (NB * SK)   // 32768
#define LN_EPS 1e-5f

// ---------------------------------------------------------------------------
// Scratch (device globals)
// ---------------------------------------------------------------------------
__device__ __half g_xh  [(size_t)MQ  * DD];
__device__ __half g_srch[(size_t)MKV * DD];
__device__ __half g_qh  [(size_t)MQ  * DD];
__device__ __half g_kh  [(size_t)MKV * DD];
__device__ __half g_vh  [(size_t)MKV * DD];
__device__ __half g_vt  [(size_t)MKV * DD];          // per batch [D,S]
__device__ __half g_sch [(size_t)NB * LQ * SK];      // dist -> attn fp16 (in place)
__device__ __half g_msgh[(size_t)MQ * DD];
__device__ __half g_hh  [(size_t)MQ * 2 * DD];
__device__ __half g_fc1h[(size_t)MQ * 2 * DD];
__device__ __half g_wqt [DD * DD];
__device__ __half g_wkt [DD * DD];
__device__ __half g_wvt [DD * DD];
__device__ __half g_wmt [DD * DD];
__device__ __half g_w1t [2 * DD * 2 * DD];
__device__ __half g_w2t [DD * 2 * DD];
__device__ float  g_tmp [(size_t)MQ * DD];
__device__ float  g_q2  [MQ];
__device__ float  g_k2  [MKV];

// ---------------------------------------------------------------------------
// PTX helpers (base compute_103 only)
// ---------------------------------------------------------------------------
__device__ __forceinline__ uint32_t cvta_smem(const void* p) {
    uint32_t a;
    asm("{ .reg .u64 t; cvta.to.shared.u64 t, %1; cvt.u32.u64 %0, t; }"
        : "=r"(a) : "l"(p));
    return a;
}
__device__ __forceinline__ void cp16(uint32_t d, const void* s) {
    asm volatile("cp.async.cg.shared.global [%0], [%1], 16;"
                 :: "r"(d), "l"(s));
}
__device__ __forceinline__ void cp_commit() {
    asm volatile("cp.async.commit_group;" ::: "memory");
}
template <int N>
__device__ __forceinline__ void cp_wait() {
    asm volatile("cp.async.wait_group %0;" :: "n"(N) : "memory");
}
__device__ __forceinline__ void ldsm4(uint32_t* r, uint32_t addr) {
    asm volatile("ldmatrix.sync.aligned.m8n8.x4.shared.b16 {%0,%1,%2,%3}, [%4];"
        : "=r"(r[0]), "=r"(r[1]), "=r"(r[2]), "=r"(r[3]) : "r"(addr));
}
__device__ __forceinline__ void mma_fp16(float* c, const uint32_t* a,
                                         const uint32_t* b) {
    asm volatile(
        "mma.sync.aligned.m16n8k16.row.col.f32.f16.f16.f32 "
        "{%0,%1,%2,%3}, {%4,%5,%6,%7}, {%8,%9}, {%0,%1,%2,%3};"
        : "+f"(c[0]), "+f"(c[1]), "+f"(c[2]), "+f"(c[3])
        : "r"(a[0]), "r"(a[1]), "r"(a[2]), "r"(a[3]),
          "r"(b[0]), "r"(b[1]));
}

// ---------------------------------------------------------------------------
// fp16 NT GEMM: C[M,Nc] = A[M,K] @ B[Nc,K]^T   (fp32 accumulate)
// Block tile 128x256x32, 8 warps (2x4) of 64x64 warp tiles, 3-stage cp.async,
// ldmatrix.x4 fragment loads. M%128==0, Nc%256==0, K%32==0, K>=64.
// DIST: C = sqrt(max(q2[row] + k2[col] - 2*acc, 0)) stored as fp16.
// ---------------------------------------------------------------------------
constexpr int ASTR = 40;                 // halfs per smem row
constexpr int AT_H = 128 * ASTR;         // 5120 halfs
constexpr int BT_H = 256 * ASTR;         // 10240 halfs
constexpr int STAGE_H = AT_H + BT_H;     // 15360 halfs = 30720 B
#define SMEM_GEMM (3 * STAGE_H * 2)      // 92160 B

template <bool RELU, typename TOUT, bool DIST>
__global__ __launch_bounds__(256, 1) void hgemm(
    const __half* __restrict__ A, const __half* __restrict__ B,
    TOUT* __restrict__ C, int M, int Nc, int K,
    long sA, long sB, long sC,
    const float* __restrict__ q2, const float* __restrict__ k2)
{
    extern __shared__ __align__(16) __half smh[];
    A += (long)blockIdx.z * sA;
    B += (long)blockIdx.z * sB;
    C += (long)blockIdx.z * sC;
    const float* q2p = DIST ? q2 + (long)blockIdx.z * LQ : nullptr;
    const float* k2p = DIST ? k2 + (long)blockIdx.z * SK : nullptr;

    const int tid = threadIdx.x, lane = tid & 31, wid = tid >> 5;
    const int wm = wid >> 2, wn = wid & 3;       // 2 x 4 warp grid
    const int row0 = blockIdx.y * 128, col0 = blockIdx.x * 256;
    const uint32_t smb = cvta_smem(smh);

    float acc[4][8][4];
    #pragma unroll
    for (int i = 0; i < 4; i++)
        #pragma unroll
        for (int j = 0; j < 8; j++)
            #pragma unroll
            for (int l = 0; l < 4; l++) acc[i][j][l] = 0.f;

    const int nt = K >> 5;

    auto load_stage = [&](int s, int t) {
        const int k0 = t << 5;
        uint32_t sa = smb + (uint32_t)(s * STAGE_H * 2);
        const __half* ga = A + (long)row0 * K + k0;
        #pragma unroll
        for (int i = 0; i < 2; i++) {
            int id = tid + (i << 8);
            int r = id >> 2, c = id & 3;
            cp16(sa + (uint32_t)(r * 80 + c * 16), ga + (long)r * K + (c << 3));
        }
        uint32_t sb = smb + (uint32_t)((s * STAGE_H + AT_H) * 2);
        const __half* gb = B + (long)col0 * K + k0;
        #pragma unroll
        for (int i = 0; i < 4; i++) {
            int id = tid + (i << 8);
            int r = id >> 2, c = id & 3;
            cp16(sb + (uint32_t)(r * 80 + c * 16), gb + (long)r * K + (c << 3));
        }
        cp_commit();
    };

    // ldmatrix per-lane source rows/cols (in halfs)
    const int a_row = (lane & 7) + ((lane >> 3) & 1) * 8;   // +8 for lanes 8-15,24-31
    const int a_kof = (lane >> 4) * 8;                      // +8 halfs for lanes 16-31
    const int b_nof = (lane & 7) + ((lane >> 4) ? 8 : 0);   // +8 rows for lanes 16-31
    const int b_kof = ((lane >> 3) & 1) * 8;                // +8 halfs for lanes 8-15,24-31

    load_stage(0, 0);
    load_stage(1, 1);

    for (int t = 0; t < nt; t++) {
        const int s = t % 3;
        if (t + 1 < nt) cp_wait<1>(); else cp_wait<0>();
        __syncthreads();
        if (t + 2 < nt) load_stage((t + 2) % 3, t + 2);

        const uint32_t sa = smb + (uint32_t)(s * STAGE_H * 2);
        const uint32_t sb = smb + (uint32_t)((s * STAGE_H + AT_H) * 2);

        #pragma unroll
        for (int ks = 0; ks < 2; ks++) {
            uint32_t af[4][4];
            #pragma unroll
            for (int ma = 0; ma < 4; ma++) {
                uint32_t ad = sa + (uint32_t)(((wm * 64 + ma * 16 + a_row) * ASTR
                                               + ks * 16 + a_kof) * 2);
                ldsm4(af[ma], ad);
            }
            uint32_t bf[8][2];
            #pragma unroll
            for (int p = 0; p < 4; p++) {
                uint32_t bd = sb + (uint32_t)(((wn * 64 + p * 16 + b_nof) * ASTR
                                               + ks * 16 + b_kof) * 2);
                ldsm4(&bf[2 * p][0], bd);
            }
            #pragma unroll
            for (int ma = 0; ma < 4; ma++)
                #pragma unroll
                for (int na = 0; na < 8; na++)
                    mma_fp16(acc[ma][na], af[ma], bf[na]);
        }
        __syncthreads();
    }

    // Epilogue
    #pragma unroll
    for (int ma = 0; ma < 4; ma++) {
        int r = row0 + wm * 64 + ma * 16 + (lane >> 2);
        float q2v0 = 0.f, q2v1 = 0.f;
        if (DIST) { q2v0 = q2p[r]; q2v1 = q2p[r + 8]; }
        #pragma unroll
        for (int na = 0; na < 8; na++) {
            int cc = col0 + wn * 64 + na * 8 + 2 * (lane & 3);
            float c0 = acc[ma][na][0], c1 = acc[ma][na][1];
            float c2 = acc[ma][na][2], c3 = acc[ma][na][3];
            if (DIST) {
                float k2v0 = k2p[cc], k2v1 = k2p[cc + 1];
                c0 = sqrtf(fmaxf(q2v0 + k2v0 - 2.f * c0, 0.f));
                c1 = sqrtf(fmaxf(q2v0 + k2v1 - 2.f * c1, 0.f));
                c2 = sqrtf(fmaxf(q2v1 + k2v0 - 2.f * c2, 0.f));
                c3 = sqrtf(fmaxf(q2v1 + k2v1 - 2.f * c3, 0.f));
            }
            if (RELU) {
                c0 = fmaxf(c0, 0.f); c1 = fmaxf(c1, 0.f);
                c2 = fmaxf(c2, 0.f); c3 = fmaxf(c3, 0.f);
            }
            if (sizeof(TOUT) == 2) {
                *(__half2*)((__half*)C + (long)r * Nc + cc) =
                    __floats2half2_rn(c0, c1);
                *(__half2*)((__half*)C + (long)(r + 8) * Nc + cc) =
                    __floats2half2_rn(c2, c3);
            } else {
                *(float2*)((float*)C + (long)r * Nc + cc) = make_float2(c0, c1);
                *(float2*)((float*)C + (long)(r + 8) * Nc + cc) = make_float2(c2, c3);
            }
        }
    }
}

// ---------------------------------------------------------------------------
// Conversion / transpose kernels
// ---------------------------------------------------------------------------
__global__ __launch_bounds__(256) void conv_f2h(
    const float* __restrict__ in, __half* __restrict__ out)
{
    long i = ((long)blockIdx.x * 256 + threadIdx.x) * 4;
    float4 v = *(const float4*)(in + i);
    *(__half2*)(out + i)     = __floats2half2_rn(v.x, v.y);
    *(__half2*)(out + i + 2) = __floats2half2_rn(v.z, v.w);
}

__global__ void trans_f2h(const float* __restrict__ in, __half* __restrict__ out,
                          int R, int C)
{
    __shared__ float t[32][33];
    int c0 = blockIdx.x * 32, r0 = blockIdx.y * 32;
    #pragma unroll
    for (int i = threadIdx.y; i < 32; i += 8)
        t[i][threadIdx.x] = in[(long)(r0 + i) * C + c0 + threadIdx.x];
    __syncthreads();
    #pragma unroll
    for (int i = threadIdx.y; i < 32; i += 8)
        out[(long)(c0 + i) * R + r0 + threadIdx.x] = __float2half_rn(t[threadIdx.x][i]);
}

__global__ void trans_h2h(const __half* __restrict__ in, __half* __restrict__ out,
                          int R, int C)
{
    __shared__ __half t[32][33];
    long bi = (long)blockIdx.z * R * C;
    int c0 = blockIdx.x * 32, r0 = blockIdx.y * 32;
    #pragma unroll
    for (int i = threadIdx.y; i < 32; i += 8)
        t[i][threadIdx.x] = in[bi + (long)(r0 + i) * C + c0 + threadIdx.x];
    __syncthreads();
    #pragma unroll
    for (int i = threadIdx.y; i < 32; i += 8)
        out[bi + (long)(c0 + i) * R + r0 + threadIdx.x] = t[threadIdx.x][i];
}

// ---------------------------------------------------------------------------
// Reductions
// ---------------------------------------------------------------------------
__device__ __forceinline__ float warpSum(float v) {
    #pragma unroll
    for (int o = 16; o > 0; o >>= 1) v += __shfl_xor_sync(0xffffffffu, v, o);
    return v;
}
__device__ __forceinline__ float warpMax(float v) {
    #pragma unroll
    for (int o = 16; o > 0; o >>= 1) v = fmaxf(v, __shfl_xor_sync(0xffffffffu, v, o));
    return v;
}
__device__ float blockSum(float v) {
    __shared__ float sh[8];
    __shared__ float tot;
    __syncthreads();
    int lane = threadIdx.x & 31, w = threadIdx.x >> 5;
    v = warpSum(v);
    if (lane == 0) sh[w] = v;
    __syncthreads();
    if (w == 0) {
        float t = (threadIdx.x < (blockDim.x >> 5)) ? sh[threadIdx.x] : 0.f;
        t = warpSum(t);
        if (threadIdx.x == 0) tot = t;
    }
    __syncthreads();
    return tot;
}
__device__ float blockMax(float v) {
    __shared__ float sh[8];
    __shared__ float tot;
    __syncthreads();
    int lane = threadIdx.x & 31, w = threadIdx.x >> 5;
    v = warpMax(v);
    if (lane == 0) sh[w] = v;
    __syncthreads();
    if (w == 0) {
        float t = (threadIdx.x < (blockDim.x >> 5)) ? sh[threadIdx.x] : -INFINITY;
        t = warpMax(t);
        if (threadIdx.x == 0) tot = t;
    }
    __syncthreads();
    return tot;
}

// ---------------------------------------------------------------------------
// Elementwise kernels
// ---------------------------------------------------------------------------
__global__ __launch_bounds__(256) void rownorm_h(
    const __half* __restrict__ X, float* __restrict__ out)
{
    const __half2* x = (const __half2*)(X + (long)blockIdx.x * DD);
    float2 f = __half22float2(x[threadIdx.x]);
    float s = blockSum(f.x * f.x + f.y * f.y);
    if (threadIdx.x == 0) out[blockIdx.x] = s;
}

// softmax over fp16 dist row (in place): attn = softmax(dist)
__global__ __launch_bounds__(256) void softmax_k(__half* __restrict__ dist)
{
    __half2* row = (__half2*)(dist + (long)blockIdx.x * SK);

    float d[16];
    float mx = -INFINITY;
    #pragma unroll
    for (int i = 0; i < 8; i++) {
        int j = threadIdx.x + i * 256;
        float2 f = __half22float2(row[j]);
        d[2 * i] = f.x; d[2 * i + 1] = f.y;
        mx = fmaxf(mx, fmaxf(f.x, f.y));
    }
    mx = blockMax(mx);

    float s = 0.f;
    #pragma unroll
    for (int i = 0; i < 16; i++) {
        d[i] = expf(d[i] - mx);
        s += d[i];
    }
    s = blockSum(s);
    float inv = 1.f / s;
    #pragma unroll
    for (int i = 0; i < 8; i++) {
        int j = threadIdx.x + i * 256;
        row[j] = __floats2half2_rn(d[2 * i] * inv, d[2 * i + 1] * inv);
    }
}

__global__ __launch_bounds__(256) void ln1_pack_k(
    const float* __restrict__ mm, const float* __restrict__ x,
    const float* __restrict__ g, const float* __restrict__ b,
    __half* __restrict__ h)
{
    const int row = blockIdx.x;
    const float* m = mm + (long)row * DD;
    const int c0 = threadIdx.x, c1 = threadIdx.x + 256;
    float v0 = m[c0], v1 = m[c1];
    float mean = blockSum(v0 + v1) * (1.f / DD);
    float var  = blockSum(v0 * v0 + v1 * v1) * (1.f / DD) - mean * mean;
    float inv = rsqrtf(var + LN_EPS);

    __half* hr = h + (long)row * (2 * DD);
    const float* xr = x + (long)row * DD;
    hr[c0] = __float2half_rn(xr[c0]);
    hr[c1] = __float2half_rn(xr[c1]);
    hr[DD + c0] = __float2half_rn((v0 - mean) * inv * g[c0] + b[c0]);
    hr[DD + c1] = __float2half_rn((v1 - mean) * inv * g[c1] + b[c1]);
}

__global__ __launch_bounds__(256) void ln2_add_k(
    const float* __restrict__ t, const float* __restrict__ x,
    const float* __restrict__ g, const float* __restrict__ b,
    float* __restrict__ out)
{
    const int row = blockIdx.x;
    const float* tr = t + (long)row * DD;
    const int c0 = threadIdx.x, c1 = threadIdx.x + 256;
    float v0 = tr[c0], v1 = tr[c1];
    float mean = blockSum(v0 + v1) * (1.f / DD);
    float var  = blockSum(v0 * v0 + v1 * v1) * (1.f / DD) - mean * mean;
    float inv = rsqrtf(var + LN_EPS);

    const float* xr = x + (long)row * DD;
    float* orow = out + (long)row * DD;
    orow[c0] = xr[c0] + (v0 - mean) * inv * g[c0] + b[c0];
    orow[c1] = xr[c1] + (v1 - mean) * inv * g[c1] + b[c1];
}

// ---------------------------------------------------------------------------
// Launch
// ---------------------------------------------------------------------------
extern "C" void kernel_launch(void* const* d_in, const int* in_sizes, int n_in,
                              void* d_out, int out_size)
{
    const float* x   = (const float*)d_in[0];
    const float* src = (const float*)d_in[1];
    const float* Wq  = (const float*)d_in[2];
    const float* Wk  = (const float*)d_in[3];
    const float* Wv  = (const float*)d_in[4];
    const float* Wm  = (const float*)d_in[5];
    const float* W1  = (const float*)d_in[6];
    const float* W2  = (const float*)d_in[7];
    const float* g1  = (const float*)d_in[8];
    const float* b1  = (const float*)d_in[9];
    const float* g2  = (const float*)d_in[10];
    const float* b2  = (const float*)d_in[11];
    float* out = (float*)d_out;

    __half *xh, *srch, *qh, *kh, *vh, *vt, *sch, *msgh, *hh, *fc1h;
    __half *wqt, *wkt, *wvt, *wmt, *w1t, *w2t;
    float *tmp, *q2, *k2;
    cudaGetSymbolAddress((void**)&xh,   g_xh);
    cudaGetSymbolAddress((void**)&srch, g_srch);
    cudaGetSymbolAddress((void**)&qh,   g_qh);
    cudaGetSymbolAddress((void**)&kh,   g_kh);
    cudaGetSymbolAddress((void**)&vh,   g_vh);
    cudaGetSymbolAddress((void**)&vt,   g_vt);
    cudaGetSymbolAddress((void**)&sch,  g_sch);
    cudaGetSymbolAddress((void**)&msgh, g_msgh);
    cudaGetSymbolAddress((void**)&hh,   g_hh);
    cudaGetSymbolAddress((void**)&fc1h, g_fc1h);
    cudaGetSymbolAddress((void**)&wqt,  g_wqt);
    cudaGetSymbolAddress((void**)&wkt,  g_wkt);
    cudaGetSymbolAddress((void**)&wvt,  g_wvt);
    cudaGetSymbolAddress((void**)&wmt,  g_wmt);
    cudaGetSymbolAddress((void**)&w1t,  g_w1t);
    cudaGetSymbolAddress((void**)&w2t,  g_w2t);
    cudaGetSymbolAddress((void**)&tmp,  g_tmp);
    cudaGetSymbolAddress((void**)&q2,   g_q2);
    cudaGetSymbolAddress((void**)&k2,   g_k2);

    cudaFuncSetAttribute((const void*)hgemm<false, __half, false>,
        cudaFuncAttributeMaxDynamicSharedMemorySize, SMEM_GEMM);
    cudaFuncSetAttribute((const void*)hgemm<false, float, false>,
        cudaFuncAttributeMaxDynamicSharedMemorySize, SMEM_GEMM);
    cudaFuncSetAttribute((const void*)hgemm<true, __half, false>,
        cudaFuncAttributeMaxDynamicSharedMemorySize, SMEM_GEMM);
    cudaFuncSetAttribute((const void*)hgemm<false, __half, true>,
        cudaFuncAttributeMaxDynamicSharedMemorySize, SMEM_GEMM);

    dim3 t32(32, 8, 1);

    // 0. fp16 conversions / weight transposes
    conv_f2h<<<(MQ * DD) / 1024, 256>>>(x, xh);
    conv_f2h<<<(MKV * DD) / 1024, 256>>>(src, srch);
    trans_f2h<<<dim3(DD / 32, DD / 32), t32>>>(Wq, wqt, DD, DD);
    trans_f2h<<<dim3(DD / 32, DD / 32), t32>>>(Wk, wkt, DD, DD);
    trans_f2h<<<dim3(DD / 32, DD / 32), t32>>>(Wv, wvt, DD, DD);
    trans_f2h<<<dim3(DD / 32, DD / 32), t32>>>(Wm, wmt, DD, DD);
    trans_f2h<<<dim3(2 * DD / 32, 2 * DD / 32), t32>>>(W1, w1t, 2 * DD, 2 * DD);
    trans_f2h<<<dim3(DD / 32, 2 * DD / 32), t32>>>(W2, w2t, 2 * DD, DD);

    // 1. Projections (NT, fp16 out)
    hgemm<false, __half, false><<<dim3(DD / 256, MQ / 128, 1), 256, SMEM_GEMM>>>(
        xh, wqt, qh, MQ, DD, DD, 0, 0, 0, nullptr, nullptr);
    hgemm<false, __half, false><<<dim3(DD / 256, MKV / 128, 1), 256, SMEM_GEMM>>>(
        srch, wkt, kh, MKV, DD, DD, 0, 0, 0, nullptr, nullptr);
    hgemm<false, __half, false><<<dim3(DD / 256, MKV / 128, 1), 256, SMEM_GEMM>>>(
        srch, wvt, vh, MKV, DD, DD, 0, 0, 0, nullptr, nullptr);

    // 2. Row squared norms (same quantized values the MMAs consume)
    rownorm_h<<<MQ, 256>>>(qh, q2);
    rownorm_h<<<MKV, 256>>>(kh, k2);

    // 3. v transpose per batch: [S,D] -> [D,S]
    trans_h2h<<<dim3(DD / 32, SK / 32, NB), t32>>>(vh, vt, SK, DD);

    // 4. dist = sqrt(max(q2+k2-2 q.k, 0)) fused into scores GEMM (fp16 out)
    hgemm<false, __half, true><<<dim3(SK / 256, LQ / 128, NB), 256, SMEM_GEMM>>>(
        qh, kh, sch, LQ, SK, DD,
        (long)LQ * DD, (long)SK * DD, (long)LQ * SK, q2, k2);

    // 5. softmax in place -> fp16 attn
    softmax_k<<<MQ, 256>>>(sch);

    // 6. message = attn @ v  (NT with vt, fp16 out)
    hgemm<false, __half, false><<<dim3(DD / 256, LQ / 128, NB), 256, SMEM_GEMM>>>(
        sch, vt, msgh, LQ, DD, SK,
        (long)LQ * SK, (long)DD * SK, (long)LQ * DD, nullptr, nullptr);

    // 7. mm = message @ Wm (fp32 out)
    hgemm<false, float, false><<<dim3(DD / 256, MQ / 128, 1), 256, SMEM_GEMM>>>(
        msgh, wmt, tmp, MQ, DD, DD, 0, 0, 0, nullptr, nullptr);

    // 8. h = [x | LayerNorm(mm)] (fp16)
    ln1_pack_k<<<MQ, 256>>>(tmp, x, g1, b1, hh);

    // 9. fc1 = relu(h @ W1) (fp16 out)
    hgemm<true, __half, false><<<dim3(2 * DD / 256, MQ / 128, 1), 256, SMEM_GEMM>>>(
        hh, w1t, fc1h, MQ, 2 * DD, 2 * DD, 0, 0, 0, nullptr, nullptr);

    // 10. fc2 = fc1 @ W2 (fp32 out)
    hgemm<false, float, false><<<dim3(DD / 256, MQ / 128, 1), 256, SMEM_GEMM>>>(
        fc1h, w2t, tmp, MQ, DD, 2 * DD, 0, 0, 0, nullptr, nullptr);

    // 11. out = x + LayerNorm(fc2)
    ln2_add_k<<<MQ, 256>>>(tmp, x, g2, b2, out);
}